// round 7
// baseline (speedup 1.0000x reference)
#include <cuda_runtime.h>
#include <cuda_bf16.h>
#include <math.h>

// ---------------- device scratch (no allocations allowed) ----------------
__device__ float g_attn[64 * 64];
__device__ float g_p1[32 * 512];            // after conv1+pool (pooled L=512)
__device__ float g_p2[16 * 256];            // after conv2+pool
__device__ unsigned long long g_bar;        // monotonic ticket barrier (never reset)

#define NB 64
#define NT 256

// Replay-safe grid barrier: tickets for global barrier k occupy [64k, 64k+64).
__device__ __forceinline__ void grid_bar(int tid) {
    __syncthreads();
    if (tid == 0) {
        __threadfence();
        unsigned long long t = atomicAdd(&g_bar, 1ULL);
        unsigned long long target = (t / (unsigned long long)NB) * NB + NB;
        while (*(volatile unsigned long long*)&g_bar < target) { }
        __threadfence();
    }
    __syncthreads();
}

__global__ void k_fused(const float* __restrict__ x,
                        const float* __restrict__ topo,
                        const float* __restrict__ W1,
                        const float* __restrict__ W2,
                        const float* __restrict__ c1_w, const float* __restrict__ c1_b,
                        const float* __restrict__ c2_w, const float* __restrict__ c2_b,
                        const float* __restrict__ c3_w, const float* __restrict__ c3_b,
                        const float* __restrict__ c4_w, const float* __restrict__ c4_b,
                        const float* __restrict__ c5_w, const float* __restrict__ c5_b,
                        const float* __restrict__ c6_w, const float* __restrict__ c6_b,
                        const float* __restrict__ out_w, const float* __restrict__ out_b,
                        float* __restrict__ out) {
    extern __shared__ float sm[];
    int tid = threadIdx.x;
    int blk = blockIdx.x;

    // ================= Phase 1: xmean (redundant per block) + attn row =================
    {
        float* att  = sm;            // 64
        float* hbuf = sm + 64;       // 128
        float* wbuf = sm + 192;      // 8320 (stride-65 view for W1, stride-129 for W2)
        float* xm   = sm + 8512;     // 64

        int warp = tid >> 5, lane = tid & 31;
        // each warp handles 8 channels; per channel: 32 lanes x 8 float4 = 1024 floats
        #pragma unroll
        for (int cc = 0; cc < 8; cc++) {
            int c = warp * 8 + cc;
            const float4* xr = (const float4*)(x + c * 1024);
            float s = 0.f;
            #pragma unroll
            for (int r = 0; r < 8; r++) {
                float4 v = xr[lane + 32 * r];
                s += v.x + v.y + v.z + v.w;
            }
            #pragma unroll
            for (int o = 16; o > 0; o >>= 1) s += __shfl_xor_sync(0xffffffffu, s, o);
            if (lane == 0) xm[c] = s * (1.0f / 1024.0f);
        }
        __syncthreads();
        if (tid < 64) att[tid] = xm[tid] * topo[blk * 64 + tid];

        // stage W1[blk] (128x64), smem stride 65
        {
            const float4* W1i = (const float4*)(W1 + blk * 8192);
            #pragma unroll
            for (int r = 0; r < 8; r++) {
                int v = tid + 256 * r;
                float4 q = W1i[v];
                int e = v * 4;
                int h = e >> 6, k = e & 63;
                float* d = &wbuf[h * 65 + k];
                d[0] = q.x; d[1] = q.y; d[2] = q.z; d[3] = q.w;
            }
        }
        __syncthreads();

        if (tid < 128) {
            float s = 0.f;
            const float* wr = &wbuf[tid * 65];
            #pragma unroll
            for (int k = 0; k < 64; k++) s += att[k] * wr[k];
            hbuf[tid] = fmaxf(s, 0.f);
        }
        __syncthreads();

        // stage W2[blk] (64x128), smem stride 129
        {
            const float4* W2i = (const float4*)(W2 + blk * 8192);
            #pragma unroll
            for (int r = 0; r < 8; r++) {
                int v = tid + 256 * r;
                float4 q = W2i[v];
                int e = v * 4;
                int o = e >> 7, h = e & 127;
                float* d = &wbuf[o * 129 + h];
                d[0] = q.x; d[1] = q.y; d[2] = q.z; d[3] = q.w;
            }
        }
        __syncthreads();

        if (tid < 64) {
            float s = 0.f;
            const float* wr = &wbuf[tid * 129];
            #pragma unroll
            for (int h = 0; h < 128; h++) s += hbuf[h] * wr[h];
            g_attn[blk * 64 + tid] = 1.0f / (1.0f + __expf(-s));
        }
    }
    grid_bar(tid);   // barrier 1: attn published

    // ================= Phase 2: y = attn @ x fused conv1+relu+pool, 16-wide tiles ======
    {
        float* attn_s = sm;                  // 4096
        float* xs     = sm + 4096;           // 64*20 = 1280
        float* ys     = sm + 5376;           // 1280
        float* wsm    = sm + 6656;           // 10240

        int tile = blk;                      // 64 tiles x 16 prepool positions
        int l0 = tile * 16 - 2;

        {
            const float4* a4 = (const float4*)g_attn;
            float4* d4 = (float4*)attn_s;
            #pragma unroll
            for (int r = 0; r < 4; r++) d4[tid + 256 * r] = a4[tid + 256 * r];
        }
        for (int j = tid; j < 10240; j += NT) wsm[j] = c1_w[j];
        for (int j = tid; j < 64 * 20; j += NT) {
            int k = j / 20, jj = j - k * 20;
            int gl = l0 + jj;
            xs[j] = ((unsigned)gl < 1024u) ? x[k * 1024 + gl] : 0.f;
        }
        __syncthreads();

        // GEMM: ys[c][j] = sum_k attn[c,k]*xs[k][j]  (1280 outputs, 5/thread)
        #pragma unroll
        for (int r = 0; r < 5; r++) {
            int idx = tid + 256 * r;
            int c = idx / 20, j = idx - c * 20;
            const float* ar = &attn_s[c * 64];
            float s = 0.f;
            #pragma unroll 8
            for (int k = 0; k < 64; k++) s += ar[k] * xs[k * 20 + j];
            ys[idx] = s;
        }
        __syncthreads();

        // conv1 + relu + pool: 32 oc x 8 pooled = 256 outputs, 1/thread
        {
            int o = tid >> 3, p = tid & 7;
            int lb = 2 * p;                   // halo -2 folded into ys indexing
            float z0 = c1_b[o], z1 = z0;
            const float* wo = &wsm[o * 320];
            for (int c = 0; c < 64; c++) {
                const float* yr = &ys[c * 20 + lb];
                const float* wc = &wo[c * 5];
                #pragma unroll
                for (int dt = 0; dt < 5; dt++) {
                    float w = wc[dt];
                    z0 += w * yr[dt];
                    z1 += w * yr[dt + 1];
                }
            }
            g_p1[o * 512 + tile * 8 + p] = fmaxf(fmaxf(z0, 0.f), fmaxf(z1, 0.f));
        }
    }
    grid_bar(tid);   // barrier 2: p1 published

    // ================= Phase 3: conv2+relu+pool, 64 blocks x 4 pooled positions ========
    {
        float* ps = sm;          // 32*12 = 384
        float* ws = sm + 384;    // 2560
        float* bs = sm + 2944;   // 16

        int tile = blk;          // pooled positions [4t, 4t+3] -> prepool [8t-2, 8t+9]
        int base = tile * 8 - 2;
        for (int j = tid; j < 384; j += NT) {
            int c = j / 12, m = j - c * 12;
            int g = base + m;
            ps[j] = ((unsigned)g < 512u) ? g_p1[c * 512 + g] : 0.f;
        }
        for (int j = tid; j < 2560; j += NT) ws[j] = c2_w[j];
        if (tid < 16) bs[tid] = c2_b[tid];
        __syncthreads();

        if (tid < 64) {
            int o = tid >> 2, p = tid & 3;
            float z0 = bs[o], z1 = z0;
            const float* wo = &ws[o * 160];
            for (int c = 0; c < 32; c++) {
                const float* pr = &ps[c * 12 + 2 * p];
                const float* wc = &wo[c * 5];
                #pragma unroll
                for (int dt = 0; dt < 5; dt++) {
                    float w = wc[dt];
                    z0 += w * pr[dt];
                    z1 += w * pr[dt + 1];
                }
            }
            g_p2[o * 256 + tile * 4 + p] = fmaxf(fmaxf(z0, 0.f), fmaxf(z1, 0.f));
        }
    }
    grid_bar(tid);   // barrier 3: p2 published

    if (blk != 0) return;

    // ================= Phase 4 (block 0): conv3..conv6 + final linear ==================
    {
        float* s2   = sm;             // 4096
        float* wall = sm + 4096;      // 850: w3|w4|w5|w6
        float* s3   = sm + 4960;      // 1024
        float* s4   = sm + 5984;      // 256
        float* s5   = sm + 6240;      // 64
        float* s6   = sm + 6304;      // 16
        float* w3 = wall;
        float* w4 = wall + 640;
        float* w5 = wall + 800;
        float* w6 = wall + 840;

        for (int j = tid; j < 4096; j += NT) s2[j] = g_p2[j];
        for (int j = tid; j < 850; j += NT) {
            float v;
            if (j < 640)      v = c3_w[j];
            else if (j < 800) v = c4_w[j - 640];
            else if (j < 840) v = c5_w[j - 800];
            else              v = c6_w[j - 840];
            wall[j] = v;
        }
        __syncthreads();

        // conv3: (16,256)->(8,128)
        for (int idx = tid; idx < 1024; idx += NT) {
            int o = idx >> 7, p = idx & 127;
            int l = 2 * p;
            float z0 = c3_b[o], z1 = z0;
            for (int c = 0; c < 16; c++) {
                const float* pr = &s2[c * 256];
                const float* wc = &w3[o * 80 + c * 5];
                #pragma unroll
                for (int dt = 0; dt < 5; dt++) {
                    int i0 = l + dt - 2, i1 = i0 + 1;
                    float w = wc[dt];
                    if ((unsigned)i0 < 256u) z0 += w * pr[i0];
                    if ((unsigned)i1 < 256u) z1 += w * pr[i1];
                }
            }
            s3[o * 128 + p] = fmaxf(fmaxf(z0, 0.f), fmaxf(z1, 0.f));
        }
        __syncthreads();

        // conv4: (8,128)->(4,64)
        if (tid < 256) {
            int o = tid >> 6, p = tid & 63;
            int l = 2 * p;
            float z0 = c4_b[o], z1 = z0;
            for (int c = 0; c < 8; c++) {
                const float* pr = &s3[c * 128];
                const float* wc = &w4[o * 40 + c * 5];
                #pragma unroll
                for (int dt = 0; dt < 5; dt++) {
                    int i0 = l + dt - 2, i1 = i0 + 1;
                    float w = wc[dt];
                    if ((unsigned)i0 < 128u) z0 += w * pr[i0];
                    if ((unsigned)i1 < 128u) z1 += w * pr[i1];
                }
            }
            s4[o * 64 + p] = fmaxf(fmaxf(z0, 0.f), fmaxf(z1, 0.f));
        }
        __syncthreads();

        // conv5: (4,64)->(2,32)
        if (tid < 64) {
            int o = tid >> 5, p = tid & 31;
            int l = 2 * p;
            float z0 = c5_b[o], z1 = z0;
            for (int c = 0; c < 4; c++) {
                const float* pr = &s4[c * 64];
                const float* wc = &w5[o * 20 + c * 5];
                #pragma unroll
                for (int dt = 0; dt < 5; dt++) {
                    int i0 = l + dt - 2, i1 = i0 + 1;
                    float w = wc[dt];
                    if ((unsigned)i0 < 64u) z0 += w * pr[i0];
                    if ((unsigned)i1 < 64u) z1 += w * pr[i1];
                }
            }
            s5[o * 32 + p] = fmaxf(fmaxf(z0, 0.f), fmaxf(z1, 0.f));
        }
        __syncthreads();

        // conv6: (2,32)->(1,16)
        if (tid < 16) {
            int p = tid, l = 2 * p;
            float z0 = c6_b[0], z1 = z0;
            for (int c = 0; c < 2; c++) {
                const float* pr = &s5[c * 32];
                const float* wc = &w6[c * 5];
                #pragma unroll
                for (int dt = 0; dt < 5; dt++) {
                    int i0 = l + dt - 2, i1 = i0 + 1;
                    float w = wc[dt];
                    if ((unsigned)i0 < 32u) z0 += w * pr[i0];
                    if ((unsigned)i1 < 32u) z1 += w * pr[i1];
                }
            }
            s6[p] = fmaxf(fmaxf(z0, 0.f), fmaxf(z1, 0.f));
        }
        __syncthreads();

        if (tid == 0) {
            float s = out_b[0];
            #pragma unroll
            for (int j = 0; j < 16; j++) s += s6[j] * out_w[j];
            out[0] = s;
        }
    }
}

extern "C" void kernel_launch(void* const* d_in, const int* in_sizes, int n_in,
                              void* d_out, int out_size) {
    const float* x     = (const float*)d_in[0];
    const float* topo  = (const float*)d_in[1];
    const float* W1    = (const float*)d_in[2];
    const float* W2    = (const float*)d_in[3];
    const float* c1_w  = (const float*)d_in[4];
    const float* c1_b  = (const float*)d_in[5];
    const float* c2_w  = (const float*)d_in[6];
    const float* c2_b  = (const float*)d_in[7];
    const float* c3_w  = (const float*)d_in[8];
    const float* c3_b  = (const float*)d_in[9];
    const float* c4_w  = (const float*)d_in[10];
    const float* c4_b  = (const float*)d_in[11];
    const float* c5_w  = (const float*)d_in[12];
    const float* c5_b  = (const float*)d_in[13];
    const float* c6_w  = (const float*)d_in[14];
    const float* c6_b  = (const float*)d_in[15];
    const float* out_w = (const float*)d_in[16];
    const float* out_b = (const float*)d_in[17];
    float* out = (float*)d_out;

    // dyn smem: max over phases = phase2: (4096+1280+1280+10240)*4 = 67584 B
    const int smem = 16896 * 4;
    static int configured = 0;
    if (!configured) {
        cudaFuncSetAttribute(k_fused, cudaFuncAttributeMaxDynamicSharedMemorySize, smem);
        configured = 1;
    }

    k_fused<<<NB, NT, smem>>>(x, topo, W1, W2,
                              c1_w, c1_b, c2_w, c2_b, c3_w, c3_b,
                              c4_w, c4_b, c5_w, c5_b, c6_w, c6_b,
                              out_w, out_b, out);
}

// round 8
// speedup vs baseline: 1.2809x; 1.2809x over previous
#include <cuda_runtime.h>
#include <cuda_bf16.h>
#include <math.h>

// ---------------- device scratch (no allocations allowed) ----------------
__device__ float g_xmean[64];
__device__ float g_attn[64 * 64];
__device__ float g_p1[32 * 512];            // after conv1+pool
__device__ float g_p2[16 * 256];            // after conv2+pool
__device__ unsigned long long g_bar;        // monotonic ticket counter (never reset)

#define NB 64

// ---------------- K1: fused xmean + per-net MLP -> attn rows ----------------
// 64 blocks x 256 threads. Block i: computes mean of channel i (4KB, no redundancy),
// publishes it, stages W1[i] (32KB) -- which hides the wait for the other 63 means --
// then runs the 2-layer MLP. One replay-safe ticket barrier per replay.
__global__ void k_attn2(const float* __restrict__ x,
                        const float* __restrict__ topo,
                        const float* __restrict__ W1,
                        const float* __restrict__ W2) {
    __shared__ float att[64];
    __shared__ float hbuf[128];
    __shared__ float red[8];
    __shared__ float wbuf[128 * 65];   // stride-65 view (W1) / stride-129 view (W2)
    int i = blockIdx.x, t = threadIdx.x;

    // --- own-channel mean: 256 threads x 1 float4 = 1024 floats ---
    {
        float4 v = ((const float4*)(x + i * 1024))[t];
        float s = v.x + v.y + v.z + v.w;
        #pragma unroll
        for (int o = 16; o > 0; o >>= 1) s += __shfl_xor_sync(0xffffffffu, s, o);
        if ((t & 31) == 0) red[t >> 5] = s;
        __syncthreads();
        if (t < 8) {
            s = red[t];
            #pragma unroll
            for (int o = 4; o > 0; o >>= 1) s += __shfl_xor_sync(0xffu, s, o);
            if (t == 0) {
                g_xmean[i] = s * (1.0f / 1024.0f);
                __threadfence();
                unsigned long long tk = atomicAdd(&g_bar, 1ULL);
                // stash my wait target in red[0] slot via shared? simpler: recompute below
                // target = (tk/NB)*NB + NB ; store in smem for reuse after staging
                red[1] = __ull2double_rn(0); // placeholder, not used
                ((unsigned long long*)red)[1] = (tk / (unsigned long long)NB) *
                                                 (unsigned long long)NB +
                                                 (unsigned long long)NB;
            }
        }
    }
    // no sync needed yet for wbuf staging (disjoint smem from red? red overlaps nothing of wbuf)

    // --- stage W1[i] (128x64) into smem stride 65 : hides the wait ---
    {
        const float4* W1i = (const float4*)(W1 + i * 8192);
        #pragma unroll
        for (int r = 0; r < 8; r++) {
            int v = t + 256 * r;           // 2048 float4
            float4 q = W1i[v];
            int e = v * 4;
            int h = e >> 6, k = e & 63;
            float* d = &wbuf[h * 65 + k];
            d[0] = q.x; d[1] = q.y; d[2] = q.z; d[3] = q.w;
        }
    }
    __syncthreads();   // staging done; red[] holds the ticket target

    // --- wait for all 64 channel means (should already be satisfied) ---
    if (t == 0) {
        unsigned long long target = ((unsigned long long*)red)[1];
        while (*(volatile unsigned long long*)&g_bar < target) { }
        __threadfence();
    }
    __syncthreads();

    if (t < 64) att[t] = g_xmean[t] * topo[i * 64 + t];
    __syncthreads();

    if (t < 128) {
        float s = 0.f;
        const float* wr = &wbuf[t * 65];
        #pragma unroll
        for (int k = 0; k < 64; k++) s += att[k] * wr[k];
        hbuf[t] = fmaxf(s, 0.f);
    }
    __syncthreads();

    // --- stage W2[i] (64x128) stride 129 (64*129 = 8256 <= 8320) ---
    {
        const float4* W2i = (const float4*)(W2 + i * 8192);
        #pragma unroll
        for (int r = 0; r < 8; r++) {
            int v = t + 256 * r;
            float4 q = W2i[v];
            int e = v * 4;
            int o = e >> 7, h = e & 127;
            float* d = &wbuf[o * 129 + h];
            d[0] = q.x; d[1] = q.y; d[2] = q.z; d[3] = q.w;
        }
    }
    __syncthreads();

    if (t < 64) {
        float s = 0.f;
        const float* wr = &wbuf[t * 129];
        #pragma unroll
        for (int h = 0; h < 128; h++) s += hbuf[h] * wr[h];
        g_attn[i * 64 + t] = 1.0f / (1.0f + __expf(-s));
    }
}

// ---------------- K2: y = attn @ x fused with conv1 + relu + pool ----------------
__global__ void k_y_conv1(const float* __restrict__ x,
                          const float* __restrict__ c1_w,
                          const float* __restrict__ c1_b) {
    extern __shared__ float sm[];
    float* attn_s = sm;             // 64*64
    float* xs     = sm + 4096;      // 64*36
    float* ys     = sm + 4096 + 2304;
    float* wsm    = sm + 4096 + 2304 + 2304;  // 10240

    int tile = blockIdx.x, tid = threadIdx.x;
    int l0 = tile * 32 - 2;

    {
        const float4* a4 = (const float4*)g_attn;
        float4* d4 = (float4*)attn_s;
        #pragma unroll
        for (int r = 0; r < 4; r++) d4[tid + 256 * r] = a4[tid + 256 * r];
    }
    for (int j = tid; j < 10240; j += 256) wsm[j] = c1_w[j];
    for (int j = tid; j < 64 * 36; j += 256) {
        int k = j / 36, jj = j - k * 36;
        int gl = l0 + jj;
        xs[j] = ((unsigned)gl < 1024u) ? x[k * 1024 + gl] : 0.f;
    }
    __syncthreads();

    for (int idx = tid; idx < 64 * 36; idx += 256) {
        int c = idx / 36, j = idx - c * 36;
        const float* ar = &attn_s[c * 64];
        float s = 0.f;
        #pragma unroll 8
        for (int k = 0; k < 64; k++) s += ar[k] * xs[k * 36 + j];
        ys[idx] = s;
    }
    __syncthreads();

    {
        int o = tid >> 3, p2 = tid & 7;
        int lb = 4 * p2;
        float z0 = c1_b[o], z1 = z0, z2 = z0, z3 = z0;
        const float* wo = &wsm[o * 320];
        for (int c = 0; c < 64; c++) {
            const float* yr = &ys[c * 36 + lb];
            const float* wc = &wo[c * 5];
            #pragma unroll
            for (int dt = 0; dt < 5; dt++) {
                float w = wc[dt];
                z0 += w * yr[dt];
                z1 += w * yr[dt + 1];
                z2 += w * yr[dt + 2];
                z3 += w * yr[dt + 3];
            }
        }
        float v0 = fmaxf(fmaxf(z0, 0.f), fmaxf(z1, 0.f));
        float v1 = fmaxf(fmaxf(z2, 0.f), fmaxf(z3, 0.f));
        int pg = tile * 16 + 2 * p2;
        g_p1[o * 512 + pg]     = v0;
        g_p1[o * 512 + pg + 1] = v1;
    }
}

// ---------------- K3: conv2 + relu + pool (32,512)->(16,256) ----------------
__global__ void k_conv2(const float* __restrict__ c2_w,
                        const float* __restrict__ c2_b) {
    __shared__ float ps[32 * 20];
    __shared__ float ws[16 * 32 * 5];
    __shared__ float bs[16];
    int tile = blockIdx.x, tid = threadIdx.x;
    int base = tile * 16 - 2;
    for (int j = tid; j < 640; j += 128) {
        int c = j / 20, m = j - c * 20;
        int g = base + m;
        ps[j] = ((unsigned)g < 512u) ? g_p1[c * 512 + g] : 0.f;
    }
    for (int j = tid; j < 2560; j += 128) ws[j] = c2_w[j];
    if (tid < 16) bs[tid] = c2_b[tid];
    __syncthreads();

    int o = tid >> 3, p = tid & 7;
    float z0 = bs[o], z1 = z0;
    const float* wo = &ws[o * 160];
    for (int c = 0; c < 32; c++) {
        const float* pr = &ps[c * 20 + 2 * p];
        const float* wc = &wo[c * 5];
        #pragma unroll
        for (int dt = 0; dt < 5; dt++) {
            float w = wc[dt];
            z0 += w * pr[dt];
            z1 += w * pr[dt + 1];
        }
    }
    g_p2[o * 256 + tile * 8 + p] = fmaxf(fmaxf(z0, 0.f), fmaxf(z1, 0.f));
}

// ---------------- K4: conv3..conv6 + final linear, one block ----------------
__global__ void k_tail(const float* __restrict__ c3_w, const float* __restrict__ c3_b,
                       const float* __restrict__ c4_w, const float* __restrict__ c4_b,
                       const float* __restrict__ c5_w, const float* __restrict__ c5_b,
                       const float* __restrict__ c6_w, const float* __restrict__ c6_b,
                       const float* __restrict__ out_w, const float* __restrict__ out_b,
                       float* __restrict__ out) {
    __shared__ float s2[16 * 256];
    __shared__ float s3[8 * 128];
    __shared__ float s4[4 * 64];
    __shared__ float s5[2 * 32];
    __shared__ float s6[16];
    __shared__ float wall[640 + 160 + 40 + 10];
    int tid = threadIdx.x;
    float* w3 = wall;
    float* w4 = wall + 640;
    float* w5 = wall + 800;
    float* w6 = wall + 840;

    for (int j = tid; j < 4096; j += 512) s2[j] = g_p2[j];
    for (int j = tid; j < 850; j += 512) {
        float v;
        if (j < 640)      v = c3_w[j];
        else if (j < 800) v = c4_w[j - 640];
        else if (j < 840) v = c5_w[j - 800];
        else              v = c6_w[j - 840];
        wall[j] = v;
    }
    __syncthreads();

    for (int idx = tid; idx < 1024; idx += 512) {
        int o = idx >> 7, p = idx & 127;
        int l = 2 * p;
        float z0 = c3_b[o], z1 = z0;
        for (int c = 0; c < 16; c++) {
            const float* pr = &s2[c * 256];
            const float* wc = &w3[o * 80 + c * 5];
            #pragma unroll
            for (int dt = 0; dt < 5; dt++) {
                int i0 = l + dt - 2, i1 = i0 + 1;
                float w = wc[dt];
                if ((unsigned)i0 < 256u) z0 += w * pr[i0];
                if ((unsigned)i1 < 256u) z1 += w * pr[i1];
            }
        }
        s3[o * 128 + p] = fmaxf(fmaxf(z0, 0.f), fmaxf(z1, 0.f));
    }
    __syncthreads();

    if (tid < 256) {
        int o = tid >> 6, p = tid & 63;
        int l = 2 * p;
        float z0 = c4_b[o], z1 = z0;
        for (int c = 0; c < 8; c++) {
            const float* pr = &s3[c * 128];
            const float* wc = &w4[o * 40 + c * 5];
            #pragma unroll
            for (int dt = 0; dt < 5; dt++) {
                int i0 = l + dt - 2, i1 = i0 + 1;
                float w = wc[dt];
                if ((unsigned)i0 < 128u) z0 += w * pr[i0];
                if ((unsigned)i1 < 128u) z1 += w * pr[i1];
            }
        }
        s4[o * 64 + p] = fmaxf(fmaxf(z0, 0.f), fmaxf(z1, 0.f));
    }
    __syncthreads();

    if (tid < 64) {
        int o = tid >> 5, p = tid & 31;
        int l = 2 * p;
        float z0 = c5_b[o], z1 = z0;
        for (int c = 0; c < 4; c++) {
            const float* pr = &s4[c * 64];
            const float* wc = &w5[o * 20 + c * 5];
            #pragma unroll
            for (int dt = 0; dt < 5; dt++) {
                int i0 = l + dt - 2, i1 = i0 + 1;
                float w = wc[dt];
                if ((unsigned)i0 < 64u) z0 += w * pr[i0];
                if ((unsigned)i1 < 64u) z1 += w * pr[i1];
            }
        }
        s5[o * 32 + p] = fmaxf(fmaxf(z0, 0.f), fmaxf(z1, 0.f));
    }
    __syncthreads();

    if (tid < 16) {
        int p = tid, l = 2 * p;
        float z0 = c6_b[0], z1 = z0;
        for (int c = 0; c < 2; c++) {
            const float* pr = &s5[c * 32];
            const float* wc = &w6[c * 5];
            #pragma unroll
            for (int dt = 0; dt < 5; dt++) {
                int i0 = l + dt - 2, i1 = i0 + 1;
                float w = wc[dt];
                if ((unsigned)i0 < 32u) z0 += w * pr[i0];
                if ((unsigned)i1 < 32u) z1 += w * pr[i1];
            }
        }
        s6[p] = fmaxf(fmaxf(z0, 0.f), fmaxf(z1, 0.f));
    }
    __syncthreads();

    if (tid == 0) {
        float s = out_b[0];
        #pragma unroll
        for (int j = 0; j < 16; j++) s += s6[j] * out_w[j];
        out[0] = s;
    }
}

extern "C" void kernel_launch(void* const* d_in, const int* in_sizes, int n_in,
                              void* d_out, int out_size) {
    const float* x     = (const float*)d_in[0];
    const float* topo  = (const float*)d_in[1];
    const float* W1    = (const float*)d_in[2];
    const float* W2    = (const float*)d_in[3];
    const float* c1_w  = (const float*)d_in[4];
    const float* c1_b  = (const float*)d_in[5];
    const float* c2_w  = (const float*)d_in[6];
    const float* c2_b  = (const float*)d_in[7];
    const float* c3_w  = (const float*)d_in[8];
    const float* c3_b  = (const float*)d_in[9];
    const float* c4_w  = (const float*)d_in[10];
    const float* c4_b  = (const float*)d_in[11];
    const float* c5_w  = (const float*)d_in[12];
    const float* c5_b  = (const float*)d_in[13];
    const float* c6_w  = (const float*)d_in[14];
    const float* c6_b  = (const float*)d_in[15];
    const float* out_w = (const float*)d_in[16];
    const float* out_b = (const float*)d_in[17];
    float* out = (float*)d_out;

    const int k3_smem = (4096 + 2304 + 2304 + 10240) * 4;   // 75776 B
    cudaFuncSetAttribute(k_y_conv1, cudaFuncAttributeMaxDynamicSharedMemorySize, k3_smem);

    k_attn2<<<NB, 256>>>(x, topo, W1, W2);
    k_y_conv1<<<32, 256, k3_smem>>>(x, c1_w, c1_b);
    k_conv2<<<32, 128>>>(c2_w, c2_b);
    k_tail<<<1, 512>>>(c3_w, c3_b, c4_w, c4_b, c5_w, c5_b, c6_w, c6_b, out_w, out_b, out);
}

// round 9
// speedup vs baseline: 1.5956x; 1.2457x over previous
#include <cuda_runtime.h>
#include <cuda_bf16.h>
#include <math.h>

// ---------------- device scratch (no allocations allowed) ----------------
__device__ float g_xmean[64];
__device__ float g_attn[64 * 64];
__device__ float g_p1[32 * 512];            // after conv1+pool
__device__ float g_p2[16 * 256];            // after conv2+pool
__device__ unsigned long long g_bar;        // monotonic ticket counter (never reset)

#define NB 64

// ---------------- K1: fused xmean + per-net MLP -> attn rows ----------------
__global__ void k_attn2(const float* __restrict__ x,
                        const float* __restrict__ topo,
                        const float* __restrict__ W1,
                        const float* __restrict__ W2) {
    __shared__ float att[64];
    __shared__ float hbuf[128];
    __shared__ float red[8];
    __shared__ unsigned long long s_target;
    __shared__ float wbuf[128 * 65];   // stride-65 view (W1) / stride-129 view (W2)
    int i = blockIdx.x, t = threadIdx.x;

    // --- own-channel mean: 256 threads x 1 float4 ---
    {
        float4 v = ((const float4*)(x + i * 1024))[t];
        float s = v.x + v.y + v.z + v.w;
        #pragma unroll
        for (int o = 16; o > 0; o >>= 1) s += __shfl_xor_sync(0xffffffffu, s, o);
        if ((t & 31) == 0) red[t >> 5] = s;
        __syncthreads();
        if (t < 8) {
            s = red[t];
            #pragma unroll
            for (int o = 4; o > 0; o >>= 1) s += __shfl_xor_sync(0xffu, s, o);
            if (t == 0) {
                g_xmean[i] = s * (1.0f / 1024.0f);
                __threadfence();
                unsigned long long tk = atomicAdd(&g_bar, 1ULL);
                s_target = (tk / (unsigned long long)NB) * (unsigned long long)NB
                           + (unsigned long long)NB;
            }
        }
    }

    // --- stage W1[i] (128x64) stride 65 : hides the wait for other means ---
    {
        const float4* W1i = (const float4*)(W1 + i * 8192);
        #pragma unroll
        for (int r = 0; r < 8; r++) {
            int v = t + 256 * r;
            float4 q = W1i[v];
            int e = v * 4;
            int h = e >> 6, k = e & 63;
            float* d = &wbuf[h * 65 + k];
            d[0] = q.x; d[1] = q.y; d[2] = q.z; d[3] = q.w;
        }
    }
    __syncthreads();

    if (t == 0) {
        unsigned long long target = s_target;
        while (*(volatile unsigned long long*)&g_bar < target) { }
        __threadfence();
    }
    __syncthreads();

    if (t < 64) att[t] = g_xmean[t] * topo[i * 64 + t];
    __syncthreads();

    if (t < 128) {
        float s = 0.f;
        const float* wr = &wbuf[t * 65];
        #pragma unroll
        for (int k = 0; k < 64; k++) s += att[k] * wr[k];
        hbuf[t] = fmaxf(s, 0.f);
    }
    __syncthreads();

    // --- stage W2[i] (64x128) stride 129 ---
    {
        const float4* W2i = (const float4*)(W2 + i * 8192);
        #pragma unroll
        for (int r = 0; r < 8; r++) {
            int v = t + 256 * r;
            float4 q = W2i[v];
            int e = v * 4;
            int o = e >> 7, h = e & 127;
            float* d = &wbuf[o * 129 + h];
            d[0] = q.x; d[1] = q.y; d[2] = q.z; d[3] = q.w;
        }
    }
    __syncthreads();

    if (t < 64) {
        float s = 0.f;
        const float* wr = &wbuf[t * 129];
        #pragma unroll
        for (int h = 0; h < 128; h++) s += hbuf[h] * wr[h];
        g_attn[i * 64 + t] = 1.0f / (1.0f + __expf(-s));
    }
}

// ---------------- K2: y = attn @ x fused with conv1 + relu + pool ----------------
__global__ void k_y_conv1(const float* __restrict__ x,
                          const float* __restrict__ c1_w,
                          const float* __restrict__ c1_b) {
    extern __shared__ float sm[];
    float* attn_s = sm;             // 4096
    float* xs     = sm + 4096;      // 2304
    float* ys     = sm + 6400;      // 2304
    float* wsm    = sm + 8704;      // 10240

    int tile = blockIdx.x, tid = threadIdx.x;
    int l0 = tile * 32 - 2;

    {
        const float4* a4 = (const float4*)g_attn;
        float4* d4 = (float4*)attn_s;
        #pragma unroll
        for (int r = 0; r < 4; r++) d4[tid + 256 * r] = a4[tid + 256 * r];
    }
    {   // weights via float4: 2560 float4, 10/thread
        const float4* w4 = (const float4*)c1_w;
        float4* d4 = (float4*)wsm;
        #pragma unroll
        for (int r = 0; r < 10; r++) d4[tid + 256 * r] = w4[tid + 256 * r];
    }
    for (int j = tid; j < 64 * 36; j += 256) {
        int k = j / 36, jj = j - k * 36;
        int gl = l0 + jj;
        xs[j] = ((unsigned)gl < 1024u) ? x[k * 1024 + gl] : 0.f;
    }
    __syncthreads();

    for (int idx = tid; idx < 64 * 36; idx += 256) {
        int c = idx / 36, j = idx - c * 36;
        const float* ar = &attn_s[c * 64];
        float s = 0.f;
        #pragma unroll 8
        for (int k = 0; k < 64; k++) s += ar[k] * xs[k * 36 + j];
        ys[idx] = s;
    }
    __syncthreads();

    {
        int o = tid >> 3, p2 = tid & 7;
        int lb = 4 * p2;
        float z0 = c1_b[o], z1 = z0, z2 = z0, z3 = z0;
        const float* wo = &wsm[o * 320];
        for (int c = 0; c < 64; c++) {
            const float* yr = &ys[c * 36 + lb];
            const float* wc = &wo[c * 5];
            #pragma unroll
            for (int dt = 0; dt < 5; dt++) {
                float w = wc[dt];
                z0 += w * yr[dt];
                z1 += w * yr[dt + 1];
                z2 += w * yr[dt + 2];
                z3 += w * yr[dt + 3];
            }
        }
        float v0 = fmaxf(fmaxf(z0, 0.f), fmaxf(z1, 0.f));
        float v1 = fmaxf(fmaxf(z2, 0.f), fmaxf(z3, 0.f));
        int pg = tile * 16 + 2 * p2;
        g_p1[o * 512 + pg]     = v0;
        g_p1[o * 512 + pg + 1] = v1;
    }
}

// ---------------- K3: conv2 + relu + pool (32,512)->(16,256) ----------------
// 32 blocks x 256 threads; 1 prepool value/thread, pool via shfl.
__global__ void k_conv2(const float* __restrict__ c2_w,
                        const float* __restrict__ c2_b) {
    __shared__ float ps[32 * 20];
    __shared__ float ws[2560];
    __shared__ float bs[16];
    int tile = blockIdx.x, tid = threadIdx.x;
    int base = tile * 16 - 2;

    {   // weights via float4: 640 float4, 2.5/thread
        const float4* w4 = (const float4*)c2_w;
        float4* d4 = (float4*)ws;
        d4[tid]       = w4[tid];
        d4[tid + 256] = w4[tid + 256];
        if (tid < 128) d4[tid + 512] = w4[tid + 512];
    }
    for (int j = tid; j < 640; j += 256) {
        int c = j / 20, m = j - c * 20;
        int g = base + m;
        ps[j] = ((unsigned)g < 512u) ? g_p1[c * 512 + g] : 0.f;
    }
    if (tid < 16) bs[tid] = c2_b[tid];
    __syncthreads();

    // 256 threads = 16 oc x 16 prepool positions; pooled via lane-pair max
    int o = tid >> 4, pp = tid & 15;
    float z = bs[o];
    const float* wo = &ws[o * 160];
    const float* pb = &ps[pp];
    for (int c = 0; c < 32; c++) {
        const float* pr = pb + c * 20;
        const float* wc = &wo[c * 5];
        #pragma unroll
        for (int dt = 0; dt < 5; dt++) z += wc[dt] * pr[dt];
    }
    z = fmaxf(z, 0.f);
    float zn = __shfl_xor_sync(0xffffffffu, z, 1);
    if ((pp & 1) == 0)
        g_p2[o * 256 + tile * 8 + (pp >> 1)] = fmaxf(z, zn);
}

// ---------------- K4: conv3..conv6 + final linear, one block x 1024 threads ---------
// Padded smem rows (zeroed halos) -> no bounds predicates in any conv loop.
__global__ void __launch_bounds__(1024, 1)
k_tail(const float* __restrict__ c3_w, const float* __restrict__ c3_b,
       const float* __restrict__ c4_w, const float* __restrict__ c4_b,
       const float* __restrict__ c5_w, const float* __restrict__ c5_b,
       const float* __restrict__ c6_w, const float* __restrict__ c6_b,
       const float* __restrict__ out_w, const float* __restrict__ out_b,
       float* __restrict__ out) {
    // row layout: [4 pad][payload][pad...]; interior starts at +4 (16B aligned)
    __shared__ float s2p[16 * 264];   // payload 256
    __shared__ float s3p[8 * 136];    // payload 128
    __shared__ float s4p[4 * 72];     // payload 64
    __shared__ float s5p[2 * 40];     // payload 32
    __shared__ float s6[16];
    __shared__ float wall[850];       // w3|w4|w5|w6
    int tid = threadIdx.x;
    float* w3 = wall;
    float* w4 = wall + 640;
    float* w5 = wall + 800;
    float* w6 = wall + 840;

    // zero all padded buffers (covers halos)
    for (int j = tid; j < 16 * 264; j += 1024) s2p[j] = 0.f;
    for (int j = tid; j < 8 * 136 + 4 * 72 + 2 * 40; j += 1024) {
        if (j < 8 * 136) s3p[j] = 0.f;
        else if (j < 8 * 136 + 4 * 72) s4p[j - 8 * 136] = 0.f;
        else s5p[j - 8 * 136 - 4 * 72] = 0.f;
    }
    if (tid < 850) wall[tid] = (tid < 640) ? c3_w[tid]
                       : (tid < 800) ? c4_w[tid - 640]
                       : (tid < 840) ? c5_w[tid - 800]
                       : c6_w[tid - 840];
    __syncthreads();

    // stage s2 interior via float4: 1024 float4, 1/thread
    {
        const float4* g4 = (const float4*)g_p2;
        float4 q = g4[tid];
        int c = tid >> 6, qq = (tid & 63) * 4;
        *(float4*)&s2p[c * 264 + 4 + qq] = q;
    }
    __syncthreads();

    // conv3: (16,256)->(8,128), 1024 outputs, 1/thread
    {
        int o = tid >> 7, p = tid & 127;
        int l = 2 * p;
        float z0 = c3_b[o], z1 = z0;
        const float* wo = &w3[o * 80];
        for (int c = 0; c < 16; c++) {
            const float* pr = &s2p[c * 264 + l + 2];   // +4 base, -2 halo
            const float* wc = &wo[c * 5];
            #pragma unroll
            for (int dt = 0; dt < 5; dt++) {
                float w = wc[dt];
                z0 += w * pr[dt];
                z1 += w * pr[dt + 1];
            }
        }
        s3p[o * 136 + 4 + p] = fmaxf(fmaxf(z0, 0.f), fmaxf(z1, 0.f));
    }
    __syncthreads();

    // conv4: (8,128)->(4,64), 256 outputs
    if (tid < 256) {
        int o = tid >> 6, p = tid & 63;
        int l = 2 * p;
        float z0 = c4_b[o], z1 = z0;
        const float* wo = &w4[o * 40];
        for (int c = 0; c < 8; c++) {
            const float* pr = &s3p[c * 136 + l + 2];
            const float* wc = &wo[c * 5];
            #pragma unroll
            for (int dt = 0; dt < 5; dt++) {
                float w = wc[dt];
                z0 += w * pr[dt];
                z1 += w * pr[dt + 1];
            }
        }
        s4p[o * 72 + 4 + p] = fmaxf(fmaxf(z0, 0.f), fmaxf(z1, 0.f));
    }
    __syncthreads();

    // conv5: (4,64)->(2,32), 64 outputs
    if (tid < 64) {
        int o = tid >> 5, p = tid & 31;
        int l = 2 * p;
        float z0 = c5_b[o], z1 = z0;
        const float* wo = &w5[o * 20];
        for (int c = 0; c < 4; c++) {
            const float* pr = &s4p[c * 72 + l + 2];
            const float* wc = &wo[c * 5];
            #pragma unroll
            for (int dt = 0; dt < 5; dt++) {
                float w = wc[dt];
                z0 += w * pr[dt];
                z1 += w * pr[dt + 1];
            }
        }
        s5p[o * 40 + 4 + p] = fmaxf(fmaxf(z0, 0.f), fmaxf(z1, 0.f));
    }
    __syncthreads();

    // conv6: (2,32)->(1,16), 16 outputs
    if (tid < 16) {
        int l = 2 * tid;
        float z0 = c6_b[0], z1 = z0;
        for (int c = 0; c < 2; c++) {
            const float* pr = &s5p[c * 40 + l + 2];
            const float* wc = &w6[c * 5];
            #pragma unroll
            for (int dt = 0; dt < 5; dt++) {
                float w = wc[dt];
                z0 += w * pr[dt];
                z1 += w * pr[dt + 1];
            }
        }
        s6[tid] = fmaxf(fmaxf(z0, 0.f), fmaxf(z1, 0.f));
    }
    __syncthreads();

    if (tid == 0) {
        float s = out_b[0];
        #pragma unroll
        for (int j = 0; j < 16; j++) s += s6[j] * out_w[j];
        out[0] = s;
    }
}

extern "C" void kernel_launch(void* const* d_in, const int* in_sizes, int n_in,
                              void* d_out, int out_size) {
    const float* x     = (const float*)d_in[0];
    const float* topo  = (const float*)d_in[1];
    const float* W1    = (const float*)d_in[2];
    const float* W2    = (const float*)d_in[3];
    const float* c1_w  = (const float*)d_in[4];
    const float* c1_b  = (const float*)d_in[5];
    const float* c2_w  = (const float*)d_in[6];
    const float* c2_b  = (const float*)d_in[7];
    const float* c3_w  = (const float*)d_in[8];
    const float* c3_b  = (const float*)d_in[9];
    const float* c4_w  = (const float*)d_in[10];
    const float* c4_b  = (const float*)d_in[11];
    const float* c5_w  = (const float*)d_in[12];
    const float* c5_b  = (const float*)d_in[13];
    const float* c6_w  = (const float*)d_in[14];
    const float* c6_b  = (const float*)d_in[15];
    const float* out_w = (const float*)d_in[16];
    const float* out_b = (const float*)d_in[17];
    float* out = (float*)d_out;

    const int k3_smem = (4096 + 2304 + 2304 + 10240) * 4;   // 75776 B
    cudaFuncSetAttribute(k_y_conv1, cudaFuncAttributeMaxDynamicSharedMemorySize, k3_smem);

    k_attn2<<<NB, 256>>>(x, topo, W1, W2);
    k_y_conv1<<<32, 256, k3_smem>>>(x, c1_w, c1_b);
    k_conv2<<<32, 256>>>(c2_w, c2_b);
    k_tail<<<1, 1024>>>(c3_w, c3_b, c4_w, c4_b, c5_w, c5_b, c6_w, c6_b, out_w, out_b, out);
}